// round 1
// baseline (speedup 1.0000x reference)
#include <cuda_runtime.h>
#include <cuda_bf16.h>
#include <cstdint>
#include <cstdio>

#define NROWS 8192
#define DIM1  1024
#define DIM2  768
#define DOUT  256

// ---------------- scratch (static __device__ globals; no allocation) ----------------
__device__ __nv_bfloat16 g_Xb[NROWS * DIM1];     // 16 MB
__device__ __nv_bfloat16 g_Yb[NROWS * DIM2];     // 12 MB
__device__ __nv_bfloat16 g_Wxb[DOUT * DIM1];
__device__ __nv_bfloat16 g_Wyb[DOUT * DIM2];
__device__ float         g_Xp[NROWS * DOUT];     // 8 MB
__device__ float         g_Yp[NROWS * DOUT];     // 8 MB
__device__ __nv_bfloat16 g_Xn[NROWS * DOUT];     // 4 MB
__device__ __nv_bfloat16 g_Yn[NROWS * DOUT];     // 4 MB
__device__ float         g_rowsum[NROWS];
__device__ float         g_colsum[NROWS];
__device__ float         g_diag[NROWS];

// ---------------- helpers ----------------
#define SWZ(x) ((x) ^ (((x) >> 3) & 0x70))

__device__ __forceinline__ void ldsm4(uint32_t& r0, uint32_t& r1, uint32_t& r2, uint32_t& r3, uint32_t a) {
    asm volatile("ldmatrix.sync.aligned.m8n8.x4.shared.b16 {%0,%1,%2,%3}, [%4];"
                 : "=r"(r0), "=r"(r1), "=r"(r2), "=r"(r3) : "r"(a));
}

__device__ __forceinline__ void mma16816(float* c, const uint32_t* a, const uint32_t* b) {
    asm volatile("mma.sync.aligned.m16n8k16.row.col.f32.bf16.bf16.f32 "
                 "{%0,%1,%2,%3},{%4,%5,%6,%7},{%8,%9},{%0,%1,%2,%3};"
                 : "+f"(c[0]), "+f"(c[1]), "+f"(c[2]), "+f"(c[3])
                 : "r"(a[0]), "r"(a[1]), "r"(a[2]), "r"(a[3]), "r"(b[0]), "r"(b[1]));
}

__device__ __forceinline__ void cpasync16(uint32_t s, const void* g) {
    asm volatile("cp.async.cg.shared.global [%0], [%1], 16;" :: "r"(s), "l"(g));
}

// one 128x64(bf16) tile for A and B each; SW128 swizzle, 128B rows
__device__ __forceinline__ void load_tile64(const __nv_bfloat16* Ag, const __nv_bfloat16* Bg,
                                            int K, uint32_t As, uint32_t Bs, int tid) {
#pragma unroll
    for (int i = 0; i < 4; i++) {
        int c = tid + i * 256;
        int row = c >> 3, col = c & 7;
        cpasync16(As + SWZ(row * 128 + col * 16), Ag + (size_t)row * K + col * 8);
        cpasync16(Bs + SWZ(row * 128 + col * 16), Bg + (size_t)row * K + col * 8);
    }
    asm volatile("cp.async.commit_group;" ::: "memory");
}

// ---------------- NT GEMM: C[M,N] = A[M,K] * B[N,K]^T, bf16 in, fp32 accum ----------
// MODE 0: epilogue = + bias, store fp32 C (ldc = total N)
// MODE 1: epilogue = exp(acc), accumulate row sums (A index) and col sums (B index)
template <int MODE>
__global__ void __launch_bounds__(256)
gemm_nt(const __nv_bfloat16* __restrict__ A, const __nv_bfloat16* __restrict__ B,
        int K, float* __restrict__ Cout, const float* __restrict__ bias, int ldc) {
    extern __shared__ char smem[];
    const uint32_t sbase = (uint32_t)__cvta_generic_to_shared(smem);

    const int tid  = threadIdx.x;
    const int lane = tid & 31;
    const int warp = tid >> 5;
    const int wmOff = (warp >> 2) * 64;   // 2 warps along M
    const int wnOff = (warp & 3) * 32;    // 4 warps along N

    const int mBase = blockIdx.y * 128;
    const int nBase = blockIdx.x * 128;

    const __nv_bfloat16* Abase = A + (size_t)mBase * K;
    const __nv_bfloat16* Bbase = B + (size_t)nBase * K;

    float acc[4][4][4];
#pragma unroll
    for (int i = 0; i < 4; i++)
#pragma unroll
        for (int j = 0; j < 4; j++)
#pragma unroll
            for (int q = 0; q < 4; q++) acc[i][j][q] = 0.f;

    const int KT = K >> 6;
    load_tile64(Abase, Bbase, K, sbase, sbase + 32768, tid);

    for (int kt = 0; kt < KT; kt++) {
        const int stage = kt & 1;
        if (kt + 1 < KT) {
            const int ns = stage ^ 1;
            load_tile64(Abase + (kt + 1) * 64, Bbase + (kt + 1) * 64, K,
                        sbase + ns * 16384, sbase + 32768 + ns * 16384, tid);
            asm volatile("cp.async.wait_group 1;" ::: "memory");
        } else {
            asm volatile("cp.async.wait_group 0;" ::: "memory");
        }
        __syncthreads();

        const uint32_t As = sbase + stage * 16384;
        const uint32_t Bs = sbase + 32768 + stage * 16384;

#pragma unroll
        for (int ks = 0; ks < 4; ks++) {
            uint32_t a[4][4], b[4][2];
#pragma unroll
            for (int mt = 0; mt < 4; mt++) {
                int row = wmOff + mt * 16 + (lane & 15);
                int kb  = ks * 32 + ((lane >> 4) << 4);
                ldsm4(a[mt][0], a[mt][1], a[mt][2], a[mt][3], As + SWZ(row * 128 + kb));
            }
#pragma unroll
            for (int np = 0; np < 2; np++) {
                int n  = wnOff + np * 16 + (lane & 7) + ((lane >> 4) << 3);
                int kb = ks * 32 + (((lane >> 3) & 1) << 4);
                ldsm4(b[2 * np][0], b[2 * np][1], b[2 * np + 1][0], b[2 * np + 1][1],
                      Bs + SWZ(n * 128 + kb));
            }
#pragma unroll
            for (int mt = 0; mt < 4; mt++)
#pragma unroll
                for (int nt = 0; nt < 4; nt++)
                    mma16816(acc[mt][nt], a[mt], b[nt]);
        }
        __syncthreads();
    }

    if (MODE == 0) {
        // bias + fp32 store
#pragma unroll
        for (int mt = 0; mt < 4; mt++) {
            int r = mBase + wmOff + mt * 16 + (lane >> 2);
#pragma unroll
            for (int nt = 0; nt < 4; nt++) {
                int c = nBase + wnOff + nt * 8 + ((lane & 3) << 1);
                float b0 = bias[c], b1 = bias[c + 1];
                Cout[(size_t)r * ldc + c]           = acc[mt][nt][0] + b0;
                Cout[(size_t)r * ldc + c + 1]       = acc[mt][nt][1] + b1;
                Cout[(size_t)(r + 8) * ldc + c]     = acc[mt][nt][2] + b0;
                Cout[(size_t)(r + 8) * ldc + c + 1] = acc[mt][nt][3] + b1;
            }
        }
    } else {
        // exp + row/col sum reduction
        float* srow = (float*)smem;        // [128]
        float* scol = srow + 128;          // [128]
        if (tid < 256) ((float*)smem)[tid] = 0.f;  // zero srow+scol
        __syncthreads();

        float rp[4][2];   // per-thread row partials: [mt][row-half]
        float cp[4][2];   // per-thread col partials: [nt][col-in-pair]
#pragma unroll
        for (int i = 0; i < 4; i++) { rp[i][0] = rp[i][1] = 0.f; cp[i][0] = cp[i][1] = 0.f; }

#pragma unroll
        for (int mt = 0; mt < 4; mt++)
#pragma unroll
            for (int nt = 0; nt < 4; nt++) {
                float e0 = __expf(acc[mt][nt][0]);
                float e1 = __expf(acc[mt][nt][1]);
                float e2 = __expf(acc[mt][nt][2]);
                float e3 = __expf(acc[mt][nt][3]);
                rp[mt][0] += e0 + e1;
                rp[mt][1] += e2 + e3;
                cp[nt][0] += e0 + e2;
                cp[nt][1] += e1 + e3;
            }

        // row partials: reduce across the 4 lanes sharing a row (lane%4)
#pragma unroll
        for (int mt = 0; mt < 4; mt++)
#pragma unroll
            for (int h = 0; h < 2; h++) {
                float v = rp[mt][h];
                v += __shfl_xor_sync(0xffffffffu, v, 1);
                v += __shfl_xor_sync(0xffffffffu, v, 2);
                if ((lane & 3) == 0)
                    atomicAdd(&srow[wmOff + mt * 16 + 8 * h + (lane >> 2)], v);
            }
        // col partials: reduce across the 8 lanes sharing a col (lane/4)
#pragma unroll
        for (int nt = 0; nt < 4; nt++)
#pragma unroll
            for (int j = 0; j < 2; j++) {
                float v = cp[nt][j];
                v += __shfl_xor_sync(0xffffffffu, v, 4);
                v += __shfl_xor_sync(0xffffffffu, v, 8);
                v += __shfl_xor_sync(0xffffffffu, v, 16);
                if ((lane >> 2) == 0)
                    atomicAdd(&scol[wnOff + nt * 8 + ((lane & 3) << 1) + j], v);
            }
        __syncthreads();

        if (tid < 128)       atomicAdd(&g_rowsum[mBase + tid], srow[tid]);
        else if (tid < 256)  atomicAdd(&g_colsum[nBase + tid - 128], scol[tid - 128]);
    }
}

// ---------------- small kernels ----------------
__global__ void f32_to_bf16(const float* __restrict__ in, __nv_bfloat16* __restrict__ out, int n4) {
    int i = blockIdx.x * blockDim.x + threadIdx.x;
    if (i < n4) {
        float4 v = ((const float4*)in)[i];
        ((__nv_bfloat162*)out)[2 * i]     = __floats2bfloat162_rn(v.x, v.y);
        ((__nv_bfloat162*)out)[2 * i + 1] = __floats2bfloat162_rn(v.z, v.w);
    }
}

__global__ void normalize_rows(const float* __restrict__ P, __nv_bfloat16* __restrict__ Out) {
    int row = blockIdx.x;
    int t = threadIdx.x;
    float v = P[(size_t)row * DOUT + t];
    float s = v * v;
#pragma unroll
    for (int o = 16; o; o >>= 1) s += __shfl_xor_sync(0xffffffffu, s, o);
    __shared__ float ws[8];
    __shared__ float sscale;
    if ((t & 31) == 0) ws[t >> 5] = s;
    __syncthreads();
    if (t == 0) {
        float acc = 0.f;
#pragma unroll
        for (int i = 0; i < 8; i++) acc += ws[i];
        sscale = 1.0f / fmaxf(sqrtf(acc), 1e-8f);
    }
    __syncthreads();
    Out[(size_t)row * DOUT + t] = __float2bfloat16(v * sscale);
}

__global__ void zero_sums() {
    int i = blockIdx.x * blockDim.x + threadIdx.x;
    if (i < NROWS) { g_rowsum[i] = 0.f; g_colsum[i] = 0.f; }
}

__global__ void diag_dot() {
    int row  = blockIdx.x * 8 + (threadIdx.x >> 5);
    int lane = threadIdx.x & 31;
    const __nv_bfloat162* x = (const __nv_bfloat162*)(g_Xn + (size_t)row * DOUT) + lane * 4;
    const __nv_bfloat162* y = (const __nv_bfloat162*)(g_Yn + (size_t)row * DOUT) + lane * 4;
    float s = 0.f;
#pragma unroll
    for (int i = 0; i < 4; i++) {
        float2 a = __bfloat1622float2(x[i]);
        float2 b = __bfloat1622float2(y[i]);
        s += a.x * b.x + a.y * b.y;
    }
#pragma unroll
    for (int o = 16; o; o >>= 1) s += __shfl_xor_sync(0xffffffffu, s, o);
    if (lane == 0) g_diag[row] = s;
}

// out[j] = -log(pos/(colsum-pos)) - log(pos/(rowsum-pos)),  pos = exp(diag[j])
//        = log(colsum - pos) + log(rowsum - pos) - 2*diag[j]
__global__ void finalize(float* __restrict__ out) {
    int j = blockIdx.x * blockDim.x + threadIdx.x;
    if (j < NROWS) {
        float d = g_diag[j];
        float pos = __expf(d);
        out[j] = logf(g_colsum[j] - pos) + logf(g_rowsum[j] - pos) - 2.0f * d;
    }
}

// ---------------- launch ----------------
static void* sym_addr(const void* s) {
    void* p = nullptr;
    cudaGetSymbolAddress(&p, s);
    return p;
}

extern "C" void kernel_launch(void* const* d_in, const int* in_sizes, int n_in,
                              void* d_out, int out_size) {
    const float* X  = (const float*)d_in[0];
    const float* Y  = (const float*)d_in[1];
    const float* Wx = (const float*)d_in[2];
    const float* bx = (const float*)d_in[3];
    const float* Wy = (const float*)d_in[4];
    const float* by = (const float*)d_in[5];

    __nv_bfloat16* Xb  = (__nv_bfloat16*)sym_addr(g_Xb);
    __nv_bfloat16* Yb  = (__nv_bfloat16*)sym_addr(g_Yb);
    __nv_bfloat16* Wxb = (__nv_bfloat16*)sym_addr(g_Wxb);
    __nv_bfloat16* Wyb = (__nv_bfloat16*)sym_addr(g_Wyb);
    float*         Xp  = (float*)sym_addr(g_Xp);
    float*         Yp  = (float*)sym_addr(g_Yp);
    __nv_bfloat16* Xn  = (__nv_bfloat16*)sym_addr(g_Xn);
    __nv_bfloat16* Yn  = (__nv_bfloat16*)sym_addr(g_Yn);

    const int SMEM = 65536;
    cudaFuncSetAttribute(gemm_nt<0>, cudaFuncAttributeMaxDynamicSharedMemorySize, SMEM);
    cudaFuncSetAttribute(gemm_nt<1>, cudaFuncAttributeMaxDynamicSharedMemorySize, SMEM);

    // 1) fp32 -> bf16 conversions
    {
        int n4 = NROWS * DIM1 / 4;
        f32_to_bf16<<<(n4 + 255) / 256, 256>>>(X, Xb, n4);
        n4 = NROWS * DIM2 / 4;
        f32_to_bf16<<<(n4 + 255) / 256, 256>>>(Y, Yb, n4);
        n4 = DOUT * DIM1 / 4;
        f32_to_bf16<<<(n4 + 255) / 256, 256>>>(Wx, Wxb, n4);
        n4 = DOUT * DIM2 / 4;
        f32_to_bf16<<<(n4 + 255) / 256, 256>>>(Wy, Wyb, n4);
    }

    // 2) projections: Xp = Xb @ Wxb^T + bx ; Yp = Yb @ Wyb^T + by
    gemm_nt<0><<<dim3(DOUT / 128, NROWS / 128), 256, SMEM>>>(Xb, Wxb, DIM1, Xp, bx, DOUT);
    gemm_nt<0><<<dim3(DOUT / 128, NROWS / 128), 256, SMEM>>>(Yb, Wyb, DIM2, Yp, by, DOUT);

    // 3) row-normalize -> bf16
    normalize_rows<<<NROWS, DOUT>>>(Xp, Xn);
    normalize_rows<<<NROWS, DOUT>>>(Yp, Yn);

    // 4) zero accumulators
    zero_sums<<<NROWS / 256, 256>>>();

    // 5) big GEMM with exp + row/col sums (sim = Xn @ Yn^T)
    gemm_nt<1><<<dim3(NROWS / 128, NROWS / 128), 256, SMEM>>>(Xn, Yn, DOUT, nullptr, nullptr, 0);

    // 6) diag dots
    diag_dot<<<NROWS / 8, 256>>>();

    // 7) finalize
    finalize<<<NROWS / 256, 256>>>((float*)d_out);
}

// round 3
// speedup vs baseline: 1.2639x; 1.2639x over previous
#include <cuda_runtime.h>
#include <cuda_bf16.h>
#include <cstdint>

#define NROWS 8192
#define DIM1  1024
#define DIM2  768
#define DOUT  256

// ---------------- scratch (static __device__ globals; no allocation) ----------------
__device__ __nv_bfloat16 g_Xb[NROWS * DIM1];
__device__ __nv_bfloat16 g_Yb[NROWS * DIM2];
__device__ __nv_bfloat16 g_Wxb[DOUT * DIM1];
__device__ __nv_bfloat16 g_Wyb[DOUT * DIM2];
__device__ float         g_Xp[NROWS * DOUT];
__device__ float         g_Yp[NROWS * DOUT];
__device__ __nv_bfloat16 g_Xn[NROWS * DOUT];
__device__ __nv_bfloat16 g_Yn[NROWS * DOUT];
__device__ float         g_rowsum[NROWS];
__device__ float         g_colsum[NROWS];
__device__ float         g_diag[NROWS];

// ---------------- helpers ----------------
#define SWZ(x) ((x) ^ (((x) >> 3) & 0x70))

__device__ __forceinline__ void ldsm4(uint32_t& r0, uint32_t& r1, uint32_t& r2, uint32_t& r3, uint32_t a) {
    asm volatile("ldmatrix.sync.aligned.m8n8.x4.shared.b16 {%0,%1,%2,%3}, [%4];"
                 : "=r"(r0), "=r"(r1), "=r"(r2), "=r"(r3) : "r"(a));
}

__device__ __forceinline__ void mma16816(float* c, const uint32_t* a, const uint32_t* b) {
    asm volatile("mma.sync.aligned.m16n8k16.row.col.f32.bf16.bf16.f32 "
                 "{%0,%1,%2,%3},{%4,%5,%6,%7},{%8,%9},{%0,%1,%2,%3};"
                 : "+f"(c[0]), "+f"(c[1]), "+f"(c[2]), "+f"(c[3])
                 : "r"(a[0]), "r"(a[1]), "r"(a[2]), "r"(a[3]), "r"(b[0]), "r"(b[1]));
}

__device__ __forceinline__ void cpasync16(uint32_t s, const void* g) {
    asm volatile("cp.async.cg.shared.global [%0], [%1], 16;" :: "r"(s), "l"(g));
}

// ================= projections: 128x128-tile NT GEMM (proven round-1 kernel) =========
__device__ __forceinline__ void load_tile64(const __nv_bfloat16* Ag, const __nv_bfloat16* Bg,
                                            int K, uint32_t As, uint32_t Bs, int tid) {
#pragma unroll
    for (int i = 0; i < 4; i++) {
        int c = tid + i * 256;
        int row = c >> 3, col = c & 7;
        cpasync16(As + SWZ(row * 128 + col * 16), Ag + (size_t)row * K + col * 8);
        cpasync16(Bs + SWZ(row * 128 + col * 16), Bg + (size_t)row * K + col * 8);
    }
    asm volatile("cp.async.commit_group;" ::: "memory");
}

__global__ void __launch_bounds__(256)
gemm_proj(const __nv_bfloat16* __restrict__ A, const __nv_bfloat16* __restrict__ B,
          int K, float* __restrict__ Cout, const float* __restrict__ bias) {
    extern __shared__ char smem[];
    const uint32_t sbase = (uint32_t)__cvta_generic_to_shared(smem);

    const int tid  = threadIdx.x;
    const int lane = tid & 31;
    const int warp = tid >> 5;
    const int wmOff = (warp >> 2) * 64;
    const int wnOff = (warp & 3) * 32;

    const int mBase = blockIdx.y * 128;
    const int nBase = blockIdx.x * 128;

    const __nv_bfloat16* Abase = A + (size_t)mBase * K;
    const __nv_bfloat16* Bbase = B + (size_t)nBase * K;

    float acc[4][4][4];
#pragma unroll
    for (int i = 0; i < 4; i++)
#pragma unroll
        for (int j = 0; j < 4; j++)
#pragma unroll
            for (int q = 0; q < 4; q++) acc[i][j][q] = 0.f;

    const int KT = K >> 6;
    load_tile64(Abase, Bbase, K, sbase, sbase + 32768, tid);

    for (int kt = 0; kt < KT; kt++) {
        const int stage = kt & 1;
        if (kt + 1 < KT) {
            const int ns = stage ^ 1;
            load_tile64(Abase + (kt + 1) * 64, Bbase + (kt + 1) * 64, K,
                        sbase + ns * 16384, sbase + 32768 + ns * 16384, tid);
            asm volatile("cp.async.wait_group 1;" ::: "memory");
        } else {
            asm volatile("cp.async.wait_group 0;" ::: "memory");
        }
        __syncthreads();

        const uint32_t As = sbase + stage * 16384;
        const uint32_t Bs = sbase + 32768 + stage * 16384;

#pragma unroll
        for (int ks = 0; ks < 4; ks++) {
            uint32_t a[4][4], b[4][2];
#pragma unroll
            for (int mt = 0; mt < 4; mt++) {
                int row = wmOff + mt * 16 + (lane & 15);
                int kb  = ks * 32 + ((lane >> 4) << 4);
                ldsm4(a[mt][0], a[mt][1], a[mt][2], a[mt][3], As + SWZ(row * 128 + kb));
            }
#pragma unroll
            for (int np = 0; np < 2; np++) {
                int n  = wnOff + np * 16 + (lane & 7) + ((lane >> 4) << 3);
                int kb = ks * 32 + (((lane >> 3) & 1) << 4);
                ldsm4(b[2 * np][0], b[2 * np][1], b[2 * np + 1][0], b[2 * np + 1][1],
                      Bs + SWZ(n * 128 + kb));
            }
#pragma unroll
            for (int mt = 0; mt < 4; mt++)
#pragma unroll
                for (int nt = 0; nt < 4; nt++)
                    mma16816(acc[mt][nt], a[mt], b[nt]);
        }
        __syncthreads();
    }

#pragma unroll
    for (int mt = 0; mt < 4; mt++) {
        int r = mBase + wmOff + mt * 16 + (lane >> 2);
#pragma unroll
        for (int nt = 0; nt < 4; nt++) {
            int c = nBase + wnOff + nt * 8 + ((lane & 3) << 1);
            float b0 = bias[c], b1 = bias[c + 1];
            Cout[(size_t)r * DOUT + c]           = acc[mt][nt][0] + b0;
            Cout[(size_t)r * DOUT + c + 1]       = acc[mt][nt][1] + b1;
            Cout[(size_t)(r + 8) * DOUT + c]     = acc[mt][nt][2] + b0;
            Cout[(size_t)(r + 8) * DOUT + c + 1] = acc[mt][nt][3] + b1;
        }
    }
}

// ================= big GEMM: 256x128 tile, K=256, exp + row/col sums + diag ==========
// smem layout: stage s at s*49152: A (256x64 bf16, 32KB) then B (128x64 bf16, 16KB)
#define BIG_SMEM 98304

__device__ __forceinline__ void load_chunk_big(const __nv_bfloat16* Ag, const __nv_bfloat16* Bg,
                                               uint32_t As, uint32_t Bs, int tid) {
    const int K = DOUT;
#pragma unroll
    for (int i = 0; i < 8; i++) {
        int c = tid + i * 256;
        int row = c >> 3, col = c & 7;
        cpasync16(As + SWZ(row * 128 + col * 16), Ag + (size_t)row * K + col * 8);
    }
#pragma unroll
    for (int i = 0; i < 4; i++) {
        int c = tid + i * 256;
        int row = c >> 3, col = c & 7;
        cpasync16(Bs + SWZ(row * 128 + col * 16), Bg + (size_t)row * K + col * 8);
    }
    asm volatile("cp.async.commit_group;" ::: "memory");
}

__global__ void __launch_bounds__(256, 1)
gemm_big(const __nv_bfloat16* __restrict__ A, const __nv_bfloat16* __restrict__ B) {
    extern __shared__ char smem[];
    const uint32_t sb = (uint32_t)__cvta_generic_to_shared(smem);

    const int tid  = threadIdx.x;
    const int lane = tid & 31;
    const int warp = tid >> 5;
    const int wm = warp >> 1;       // 4 warps along M (64 rows each)
    const int wn = warp & 1;        // 2 warps along N (64 cols each)

    const int mBase = blockIdx.y * 256;
    const int nBase = blockIdx.x * 128;

    const __nv_bfloat16* Ab = A + (size_t)mBase * DOUT;
    const __nv_bfloat16* Bb = B + (size_t)nBase * DOUT;

    float acc[4][8][4];
#pragma unroll
    for (int i = 0; i < 4; i++)
#pragma unroll
        for (int j = 0; j < 8; j++)
#pragma unroll
            for (int q = 0; q < 4; q++) acc[i][j][q] = 0.f;

    const int KT = DOUT / 64;   // 4
    load_chunk_big(Ab, Bb, sb, sb + 32768, tid);

    for (int kt = 0; kt < KT; kt++) {
        const int stage = kt & 1;
        if (kt + 1 < KT) {
            const int ns = stage ^ 1;
            load_chunk_big(Ab + (kt + 1) * 64, Bb + (kt + 1) * 64,
                           sb + ns * 49152, sb + ns * 49152 + 32768, tid);
            asm volatile("cp.async.wait_group 1;" ::: "memory");
        } else {
            asm volatile("cp.async.wait_group 0;" ::: "memory");
        }
        __syncthreads();

        const uint32_t As = sb + stage * 49152;
        const uint32_t Bs = As + 32768;

#pragma unroll
        for (int ks = 0; ks < 4; ks++) {
            uint32_t a[4][4], b[8][2];
#pragma unroll
            for (int mt = 0; mt < 4; mt++) {
                int row = wm * 64 + mt * 16 + (lane & 15);
                int kb  = ks * 32 + ((lane >> 4) << 4);
                ldsm4(a[mt][0], a[mt][1], a[mt][2], a[mt][3], As + SWZ(row * 128 + kb));
            }
#pragma unroll
            for (int np = 0; np < 4; np++) {
                int n  = wn * 64 + np * 16 + (lane & 7) + ((lane >> 4) << 3);
                int kb = ks * 32 + (((lane >> 3) & 1) << 4);
                ldsm4(b[2 * np][0], b[2 * np][1], b[2 * np + 1][0], b[2 * np + 1][1],
                      Bs + SWZ(n * 128 + kb));
            }
#pragma unroll
            for (int mt = 0; mt < 4; mt++)
#pragma unroll
                for (int nt = 0; nt < 8; nt++)
                    mma16816(acc[mt][nt], a[mt], b[nt]);
        }
        __syncthreads();
    }

    // ---- epilogue: diag capture, exp, row/col partial sums ----
    const bool diagTile = (nBase >= mBase) && (nBase < mBase + 256);

    float rp[4][2], cp[8][2];
#pragma unroll
    for (int i = 0; i < 4; i++) rp[i][0] = rp[i][1] = 0.f;
#pragma unroll
    for (int i = 0; i < 8; i++) cp[i][0] = cp[i][1] = 0.f;

#pragma unroll
    for (int mt = 0; mt < 4; mt++) {
#pragma unroll
        for (int nt = 0; nt < 8; nt++) {
            if (diagTile) {
#pragma unroll
                for (int q = 0; q < 4; q++) {
                    int r = wm * 64 + mt * 16 + (lane >> 2) + ((q >> 1) << 3);
                    int c = wn * 64 + nt * 8 + ((lane & 3) << 1) + (q & 1);
                    if (mBase + r == nBase + c) g_diag[mBase + r] = acc[mt][nt][q];
                }
            }
            float e0 = __expf(acc[mt][nt][0]);
            float e1 = __expf(acc[mt][nt][1]);
            float e2 = __expf(acc[mt][nt][2]);
            float e3 = __expf(acc[mt][nt][3]);
            rp[mt][0] += e0 + e1;
            rp[mt][1] += e2 + e3;
            cp[nt][0] += e0 + e2;
            cp[nt][1] += e1 + e3;
        }
    }

    // rows: reduce over 4 lanes sharing a row (xor 1,2)
#pragma unroll
    for (int mt = 0; mt < 4; mt++)
#pragma unroll
        for (int h = 0; h < 2; h++) {
            float v = rp[mt][h];
            v += __shfl_xor_sync(0xffffffffu, v, 1);
            v += __shfl_xor_sync(0xffffffffu, v, 2);
            if ((lane & 3) == 0)
                atomicAdd(&g_rowsum[mBase + wm * 64 + mt * 16 + h * 8 + (lane >> 2)], v);
        }
    // cols: reduce over 8 lanes sharing a col (xor 4,8,16)
#pragma unroll
    for (int nt = 0; nt < 8; nt++)
#pragma unroll
        for (int j = 0; j < 2; j++) {
            float v = cp[nt][j];
            v += __shfl_xor_sync(0xffffffffu, v, 4);
            v += __shfl_xor_sync(0xffffffffu, v, 8);
            v += __shfl_xor_sync(0xffffffffu, v, 16);
            if (lane < 4)
                atomicAdd(&g_colsum[nBase + wn * 64 + nt * 8 + ((lane & 3) << 1) + j], v);
        }
}

// ---------------- small kernels ----------------
__global__ void conv_all(const float* __restrict__ X, const float* __restrict__ Y,
                         const float* __restrict__ Wx, const float* __restrict__ Wy) {
    const int NX = NROWS * DIM1 / 4, NY = NROWS * DIM2 / 4;
    const int NWX = DOUT * DIM1 / 4, NWY = DOUT * DIM2 / 4;
    int j = blockIdx.x * blockDim.x + threadIdx.x;
    const float* src;
    __nv_bfloat16* dst;
    if (j < NX) { src = X; dst = g_Xb; }
    else {
        j -= NX;
        if (j < NY) { src = Y; dst = g_Yb; }
        else {
            j -= NY;
            if (j < NWX) { src = Wx; dst = g_Wxb; }
            else {
                j -= NWX;
                if (j >= NWY) return;
                src = Wy; dst = g_Wyb;
            }
        }
    }
    float4 v = ((const float4*)src)[j];
    ((__nv_bfloat162*)dst)[2 * j]     = __floats2bfloat162_rn(v.x, v.y);
    ((__nv_bfloat162*)dst)[2 * j + 1] = __floats2bfloat162_rn(v.z, v.w);
}

// WHICH==0: also zeros g_rowsum[row]; WHICH==1: zeros g_colsum[row]
template <int WHICH>
__global__ void normalize_rows(const float* __restrict__ P, __nv_bfloat16* __restrict__ Out) {
    int row = blockIdx.x;
    int t = threadIdx.x;
    if (t == 0) { if (WHICH == 0) g_rowsum[row] = 0.f; else g_colsum[row] = 0.f; }
    float v = P[(size_t)row * DOUT + t];
    float s = v * v;
#pragma unroll
    for (int o = 16; o; o >>= 1) s += __shfl_xor_sync(0xffffffffu, s, o);
    __shared__ float ws[8];
    __shared__ float sscale;
    if ((t & 31) == 0) ws[t >> 5] = s;
    __syncthreads();
    if (t == 0) {
        float acc = 0.f;
#pragma unroll
        for (int i = 0; i < 8; i++) acc += ws[i];
        sscale = 1.0f / fmaxf(sqrtf(acc), 1e-8f);
    }
    __syncthreads();
    Out[(size_t)row * DOUT + t] = __float2bfloat16(v * sscale);
}

// out[j] = log(colsum - pos) + log(rowsum - pos) - 2*diag[j],  pos = exp(diag[j])
__global__ void finalize(float* __restrict__ out) {
    int j = blockIdx.x * blockDim.x + threadIdx.x;
    if (j < NROWS) {
        float d = g_diag[j];
        float pos = __expf(d);
        out[j] = logf(g_colsum[j] - pos) + logf(g_rowsum[j] - pos) - 2.0f * d;
    }
}

// ---------------- launch ----------------
static void* sym_addr(const void* s) {
    void* p = nullptr;
    cudaGetSymbolAddress(&p, s);
    return p;
}

extern "C" void kernel_launch(void* const* d_in, const int* in_sizes, int n_in,
                              void* d_out, int out_size) {
    const float* X  = (const float*)d_in[0];
    const float* Y  = (const float*)d_in[1];
    const float* Wx = (const float*)d_in[2];
    const float* bx = (const float*)d_in[3];
    const float* Wy = (const float*)d_in[4];
    const float* by = (const float*)d_in[5];

    __nv_bfloat16* Xb  = (__nv_bfloat16*)sym_addr(g_Xb);
    __nv_bfloat16* Yb  = (__nv_bfloat16*)sym_addr(g_Yb);
    __nv_bfloat16* Wxb = (__nv_bfloat16*)sym_addr(g_Wxb);
    __nv_bfloat16* Wyb = (__nv_bfloat16*)sym_addr(g_Wyb);
    float*         Xp  = (float*)sym_addr(g_Xp);
    float*         Yp  = (float*)sym_addr(g_Yp);
    __nv_bfloat16* Xn  = (__nv_bfloat16*)sym_addr(g_Xn);
    __nv_bfloat16* Yn  = (__nv_bfloat16*)sym_addr(g_Yn);

    cudaFuncSetAttribute(gemm_proj, cudaFuncAttributeMaxDynamicSharedMemorySize, 65536);
    cudaFuncSetAttribute(gemm_big,  cudaFuncAttributeMaxDynamicSharedMemorySize, BIG_SMEM);

    // 0) conversions (single kernel)
    {
        const int total4 = (NROWS * DIM1 + NROWS * DIM2 + DOUT * DIM1 + DOUT * DIM2) / 4;
        conv_all<<<(total4 + 255) / 256, 256>>>(X, Y, Wx, Wy);
    }

    // 1,2) projections
    gemm_proj<<<dim3(DOUT / 128, NROWS / 128), 256, 65536>>>(Xb, Wxb, DIM1, Xp, bx);
    gemm_proj<<<dim3(DOUT / 128, NROWS / 128), 256, 65536>>>(Yb, Wyb, DIM2, Yp, by);

    // 3,4) row-normalize -> bf16 (also zero accumulators)
    normalize_rows<0><<<NROWS, DOUT>>>(Xp, Xn);
    normalize_rows<1><<<NROWS, DOUT>>>(Yp, Yn);

    // 5) big GEMM with fused exp/rowsum/colsum/diag  (ncu -s 5 captures this one)
    gemm_big<<<dim3(NROWS / 128, NROWS / 256), 256, BIG_SMEM>>>(Xn, Yn);

    // 6) finalize
    finalize<<<NROWS / 256, 256>>>((float*)d_out);
}

// round 4
// speedup vs baseline: 1.5604x; 1.2347x over previous
#include <cuda_runtime.h>
#include <cuda_bf16.h>
#include <cstdint>

#define NROWS 8192
#define DIM1  1024
#define DIM2  768
#define DOUT  256

// ---------------- scratch (static __device__ globals; no allocation) ----------------
__device__ __nv_bfloat16 g_Xb[NROWS * DIM1];
__device__ __nv_bfloat16 g_Yb[NROWS * DIM2];
__device__ __nv_bfloat16 g_Wxb[DOUT * DIM1];
__device__ __nv_bfloat16 g_Wyb[DOUT * DIM2];
__device__ __nv_bfloat16 g_Xn[NROWS * DOUT];
__device__ __nv_bfloat16 g_Yn[NROWS * DOUT];
__device__ float         g_rowsum[NROWS];
__device__ float         g_colsum[NROWS];
__device__ float         g_diag[NROWS];

// ---------------- helpers ----------------
#define SWZ(x) ((x) ^ (((x) >> 3) & 0x70))

__device__ __forceinline__ void ldsm4(uint32_t& r0, uint32_t& r1, uint32_t& r2, uint32_t& r3, uint32_t a) {
    asm volatile("ldmatrix.sync.aligned.m8n8.x4.shared.b16 {%0,%1,%2,%3}, [%4];"
                 : "=r"(r0), "=r"(r1), "=r"(r2), "=r"(r3) : "r"(a));
}

__device__ __forceinline__ void mma16816(float* c, const uint32_t* a, const uint32_t* b) {
    asm volatile("mma.sync.aligned.m16n8k16.row.col.f32.bf16.bf16.f32 "
                 "{%0,%1,%2,%3},{%4,%5,%6,%7},{%8,%9},{%0,%1,%2,%3};"
                 : "+f"(c[0]), "+f"(c[1]), "+f"(c[2]), "+f"(c[3])
                 : "r"(a[0]), "r"(a[1]), "r"(a[2]), "r"(a[3]), "r"(b[0]), "r"(b[1]));
}

__device__ __forceinline__ void cpasync16(uint32_t s, const void* g) {
    asm volatile("cp.async.cg.shared.global [%0], [%1], 16;" :: "r"(s), "l"(g));
}

// ============== fused projection + row-normalize:  Out = normalize(A@B^T + bias) =====
// Tile: 64 rows x 256 cols (full DOUT), 512 threads.
// Warp grid: 2 along M (32 rows) x 8 along N (32 cols). Warp tile 32x32.
// smem per stage: A 64x64bf16 (8KB) + B 256x64bf16 (32KB) = 40KB; 2 stages = 80KB.
#define PROJ_SMEM 81920

__device__ __forceinline__ void load_chunk_proj(const __nv_bfloat16* Ag, const __nv_bfloat16* Bg,
                                                int K, uint32_t As, uint32_t Bs, int tid) {
    {
        int row = tid >> 3, col = tid & 7;   // 512 cells = 64 rows x 8
        cpasync16(As + SWZ(row * 128 + col * 16), Ag + (size_t)row * K + col * 8);
    }
#pragma unroll
    for (int i = 0; i < 4; i++) {
        int c = tid + i * 512;
        int row = c >> 3, col = c & 7;       // 2048 cells = 256 rows x 8
        cpasync16(Bs + SWZ(row * 128 + col * 16), Bg + (size_t)row * K + col * 8);
    }
    asm volatile("cp.async.commit_group;" ::: "memory");
}

// WHICH==0: zero g_rowsum for this row range; WHICH==1: zero g_colsum
template <int WHICH>
__global__ void __launch_bounds__(512)
proj_norm(const __nv_bfloat16* __restrict__ A, const __nv_bfloat16* __restrict__ B,
          int K, const float* __restrict__ bias, __nv_bfloat16* __restrict__ Out) {
    extern __shared__ char smem[];
    const uint32_t sb = (uint32_t)__cvta_generic_to_shared(smem);

    const int tid  = threadIdx.x;
    const int lane = tid & 31;
    const int warp = tid >> 5;
    const int wm = warp >> 3;          // 0..1
    const int wn = warp & 7;           // 0..7
    const int mBase = blockIdx.x * 64;

    const __nv_bfloat16* Ab = A + (size_t)mBase * K;

    float acc[2][4][4];
#pragma unroll
    for (int i = 0; i < 2; i++)
#pragma unroll
        for (int j = 0; j < 4; j++)
#pragma unroll
            for (int q = 0; q < 4; q++) acc[i][j][q] = 0.f;

    const int KT = K >> 6;
    load_chunk_proj(Ab, B, K, sb, sb + 8192, tid);

    for (int kt = 0; kt < KT; kt++) {
        const int stage = kt & 1;
        if (kt + 1 < KT) {
            const int ns = stage ^ 1;
            load_chunk_proj(Ab + (kt + 1) * 64, B + (kt + 1) * 64, K,
                            sb + ns * 40960, sb + ns * 40960 + 8192, tid);
            asm volatile("cp.async.wait_group 1;" ::: "memory");
        } else {
            asm volatile("cp.async.wait_group 0;" ::: "memory");
        }
        __syncthreads();

        const uint32_t As = sb + stage * 40960;
        const uint32_t Bs = As + 8192;

#pragma unroll
        for (int ks = 0; ks < 4; ks++) {
            uint32_t a[2][4], b[4][2];
#pragma unroll
            for (int mt = 0; mt < 2; mt++) {
                int row = wm * 32 + mt * 16 + (lane & 15);
                int kb  = ks * 32 + ((lane >> 4) << 4);
                ldsm4(a[mt][0], a[mt][1], a[mt][2], a[mt][3], As + SWZ(row * 128 + kb));
            }
#pragma unroll
            for (int np = 0; np < 2; np++) {
                int n  = wn * 32 + np * 16 + (lane & 7) + ((lane >> 4) << 3);
                int kb = ks * 32 + (((lane >> 3) & 1) << 4);
                ldsm4(b[2 * np][0], b[2 * np][1], b[2 * np + 1][0], b[2 * np + 1][1],
                      Bs + SWZ(n * 128 + kb));
            }
#pragma unroll
            for (int mt = 0; mt < 2; mt++)
#pragma unroll
                for (int nt = 0; nt < 4; nt++)
                    mma16816(acc[mt][nt], a[mt], b[nt]);
        }
        __syncthreads();
    }

    // ---- epilogue: bias, sumsq, cross-warp reduce, scale, bf16 store ----
    float* sred   = (float*)smem;            // [64][8]
    float* sscale = sred + 64 * 8;           // [64]

    // add bias in-place; accumulate per-(mt,h) sumsq partials
    float p[2][2] = {{0.f, 0.f}, {0.f, 0.f}};
#pragma unroll
    for (int mt = 0; mt < 2; mt++)
#pragma unroll
        for (int nt = 0; nt < 4; nt++) {
            int c = wn * 32 + nt * 8 + ((lane & 3) << 1);
            float b0 = bias[c], b1 = bias[c + 1];
            acc[mt][nt][0] += b0; acc[mt][nt][1] += b1;
            acc[mt][nt][2] += b0; acc[mt][nt][3] += b1;
            p[mt][0] += acc[mt][nt][0] * acc[mt][nt][0] + acc[mt][nt][1] * acc[mt][nt][1];
            p[mt][1] += acc[mt][nt][2] * acc[mt][nt][2] + acc[mt][nt][3] * acc[mt][nt][3];
        }
    // reduce over the 4 lanes sharing each row
#pragma unroll
    for (int mt = 0; mt < 2; mt++)
#pragma unroll
        for (int h = 0; h < 2; h++) {
            float v = p[mt][h];
            v += __shfl_xor_sync(0xffffffffu, v, 1);
            v += __shfl_xor_sync(0xffffffffu, v, 2);
            if ((lane & 3) == 0)
                sred[(wm * 32 + mt * 16 + h * 8 + (lane >> 2)) * 8 + wn] = v;
        }
    __syncthreads();
    if (tid < 64) {
        float ss = 0.f;
#pragma unroll
        for (int i = 0; i < 8; i++) ss += sred[tid * 8 + i];
        sscale[tid] = 1.0f / fmaxf(sqrtf(ss), 1e-8f);
        // zero the accumulators for the big GEMM
        if (WHICH == 0) g_rowsum[mBase + tid] = 0.f;
        else            g_colsum[mBase + tid] = 0.f;
    }
    __syncthreads();

#pragma unroll
    for (int mt = 0; mt < 2; mt++)
#pragma unroll
        for (int h = 0; h < 2; h++) {
            int r = wm * 32 + mt * 16 + h * 8 + (lane >> 2);
            float sc = sscale[r];
#pragma unroll
            for (int nt = 0; nt < 4; nt++) {
                int c = wn * 32 + nt * 8 + ((lane & 3) << 1);
                float v0 = acc[mt][nt][2 * h]     * sc;
                float v1 = acc[mt][nt][2 * h + 1] * sc;
                *(__nv_bfloat162*)(Out + (size_t)(mBase + r) * DOUT + c) =
                    __floats2bfloat162_rn(v0, v1);
            }
        }
}

// ================= big GEMM: 128x128 tile, 2 CTAs/SM, exp + row/col sums + diag ======
// smem per stage: A 16KB + B 16KB = 32KB; 2 stages = 64KB -> 2 CTAs/SM.
#define BIG_SMEM 65536

__device__ __forceinline__ void load_chunk_big(const __nv_bfloat16* Ag, const __nv_bfloat16* Bg,
                                               uint32_t As, uint32_t Bs, int tid) {
#pragma unroll
    for (int i = 0; i < 4; i++) {
        int c = tid + i * 256;
        int row = c >> 3, col = c & 7;
        cpasync16(As + SWZ(row * 128 + col * 16), Ag + (size_t)row * DOUT + col * 8);
        cpasync16(Bs + SWZ(row * 128 + col * 16), Bg + (size_t)row * DOUT + col * 8);
    }
    asm volatile("cp.async.commit_group;" ::: "memory");
}

__global__ void __launch_bounds__(256, 2)
gemm_big(const __nv_bfloat16* __restrict__ A, const __nv_bfloat16* __restrict__ B) {
    extern __shared__ char smem[];
    const uint32_t sb = (uint32_t)__cvta_generic_to_shared(smem);

    const int tid  = threadIdx.x;
    const int lane = tid & 31;
    const int warp = tid >> 5;
    const int wmOff = (warp >> 2) * 64;   // 2 warps along M
    const int wnOff = (warp & 3) * 32;    // 4 warps along N

    const int mBase = blockIdx.y * 128;
    const int nBase = blockIdx.x * 128;

    const __nv_bfloat16* Ab = A + (size_t)mBase * DOUT;
    const __nv_bfloat16* Bb = B + (size_t)nBase * DOUT;

    float acc[4][4][4];
#pragma unroll
    for (int i = 0; i < 4; i++)
#pragma unroll
        for (int j = 0; j < 4; j++)
#pragma unroll
            for (int q = 0; q < 4; q++) acc[i][j][q] = 0.f;

    const int KT = DOUT / 64;   // 4
    load_chunk_big(Ab, Bb, sb, sb + 16384, tid);

    for (int kt = 0; kt < KT; kt++) {
        const int stage = kt & 1;
        if (kt + 1 < KT) {
            const int ns = stage ^ 1;
            load_chunk_big(Ab + (kt + 1) * 64, Bb + (kt + 1) * 64,
                           sb + ns * 32768, sb + ns * 32768 + 16384, tid);
            asm volatile("cp.async.wait_group 1;" ::: "memory");
        } else {
            asm volatile("cp.async.wait_group 0;" ::: "memory");
        }
        __syncthreads();

        const uint32_t As = sb + stage * 32768;
        const uint32_t Bs = As + 16384;

#pragma unroll
        for (int ks = 0; ks < 4; ks++) {
            uint32_t a[4][4], b[4][2];
#pragma unroll
            for (int mt = 0; mt < 4; mt++) {
                int row = wmOff + mt * 16 + (lane & 15);
                int kb  = ks * 32 + ((lane >> 4) << 4);
                ldsm4(a[mt][0], a[mt][1], a[mt][2], a[mt][3], As + SWZ(row * 128 + kb));
            }
#pragma unroll
            for (int np = 0; np < 2; np++) {
                int n  = wnOff + np * 16 + (lane & 7) + ((lane >> 4) << 3);
                int kb = ks * 32 + (((lane >> 3) & 1) << 4);
                ldsm4(b[2 * np][0], b[2 * np][1], b[2 * np + 1][0], b[2 * np + 1][1],
                      Bs + SWZ(n * 128 + kb));
            }
#pragma unroll
            for (int mt = 0; mt < 4; mt++)
#pragma unroll
                for (int nt = 0; nt < 4; nt++)
                    mma16816(acc[mt][nt], a[mt], b[nt]);
        }
        __syncthreads();
    }

    // ---- epilogue: diag capture, exp, row/col partial sums ----
    const bool diagTile = (mBase == nBase);

    float rp[4][2], cp[4][2];
#pragma unroll
    for (int i = 0; i < 4; i++) { rp[i][0] = rp[i][1] = 0.f; cp[i][0] = cp[i][1] = 0.f; }

#pragma unroll
    for (int mt = 0; mt < 4; mt++) {
#pragma unroll
        for (int nt = 0; nt < 4; nt++) {
            if (diagTile) {
#pragma unroll
                for (int q = 0; q < 4; q++) {
                    int r = wmOff + mt * 16 + (lane >> 2) + ((q >> 1) << 3);
                    int c = wnOff + nt * 8 + ((lane & 3) << 1) + (q & 1);
                    if (r == c) g_diag[mBase + r] = acc[mt][nt][q];
                }
            }
            float e0 = __expf(acc[mt][nt][0]);
            float e1 = __expf(acc[mt][nt][1]);
            float e2 = __expf(acc[mt][nt][2]);
            float e3 = __expf(acc[mt][nt][3]);
            rp[mt][0] += e0 + e1;
            rp[mt][1] += e2 + e3;
            cp[nt][0] += e0 + e2;
            cp[nt][1] += e1 + e3;
        }
    }

    // rows: reduce over 4 lanes sharing a row
#pragma unroll
    for (int mt = 0; mt < 4; mt++)
#pragma unroll
        for (int h = 0; h < 2; h++) {
            float v = rp[mt][h];
            v += __shfl_xor_sync(0xffffffffu, v, 1);
            v += __shfl_xor_sync(0xffffffffu, v, 2);
            if ((lane & 3) == 0)
                atomicAdd(&g_rowsum[mBase + wmOff + mt * 16 + h * 8 + (lane >> 2)], v);
        }
    // cols: reduce over 8 lanes sharing a col
#pragma unroll
    for (int nt = 0; nt < 4; nt++)
#pragma unroll
        for (int j = 0; j < 2; j++) {
            float v = cp[nt][j];
            v += __shfl_xor_sync(0xffffffffu, v, 4);
            v += __shfl_xor_sync(0xffffffffu, v, 8);
            v += __shfl_xor_sync(0xffffffffu, v, 16);
            if (lane < 4)
                atomicAdd(&g_colsum[nBase + wnOff + nt * 8 + ((lane & 3) << 1) + j], v);
        }
}

// ---------------- small kernels ----------------
__global__ void conv_all(const float* __restrict__ X, const float* __restrict__ Y,
                         const float* __restrict__ Wx, const float* __restrict__ Wy) {
    const int NX = NROWS * DIM1 / 4, NY = NROWS * DIM2 / 4;
    const int NWX = DOUT * DIM1 / 4, NWY = DOUT * DIM2 / 4;
    int j = blockIdx.x * blockDim.x + threadIdx.x;
    const float* src;
    __nv_bfloat16* dst;
    if (j < NX) { src = X; dst = g_Xb; }
    else {
        j -= NX;
        if (j < NY) { src = Y; dst = g_Yb; }
        else {
            j -= NY;
            if (j < NWX) { src = Wx; dst = g_Wxb; }
            else {
                j -= NWX;
                if (j >= NWY) return;
                src = Wy; dst = g_Wyb;
            }
        }
    }
    float4 v = ((const float4*)src)[j];
    ((__nv_bfloat162*)dst)[2 * j]     = __floats2bfloat162_rn(v.x, v.y);
    ((__nv_bfloat162*)dst)[2 * j + 1] = __floats2bfloat162_rn(v.z, v.w);
}

// out[j] = log(colsum - pos) + log(rowsum - pos) - 2*diag[j],  pos = exp(diag[j])
__global__ void finalize(float* __restrict__ out) {
    int j = blockIdx.x * blockDim.x + threadIdx.x;
    if (j < NROWS) {
        float d = g_diag[j];
        float pos = __expf(d);
        out[j] = logf(g_colsum[j] - pos) + logf(g_rowsum[j] - pos) - 2.0f * d;
    }
}

// ---------------- launch ----------------
static void* sym_addr(const void* s) {
    void* p = nullptr;
    cudaGetSymbolAddress(&p, s);
    return p;
}

extern "C" void kernel_launch(void* const* d_in, const int* in_sizes, int n_in,
                              void* d_out, int out_size) {
    const float* X  = (const float*)d_in[0];
    const float* Y  = (const float*)d_in[1];
    const float* Wx = (const float*)d_in[2];
    const float* bx = (const float*)d_in[3];
    const float* Wy = (const float*)d_in[4];
    const float* by = (const float*)d_in[5];

    __nv_bfloat16* Xb  = (__nv_bfloat16*)sym_addr(g_Xb);
    __nv_bfloat16* Yb  = (__nv_bfloat16*)sym_addr(g_Yb);
    __nv_bfloat16* Wxb = (__nv_bfloat16*)sym_addr(g_Wxb);
    __nv_bfloat16* Wyb = (__nv_bfloat16*)sym_addr(g_Wyb);
    __nv_bfloat16* Xn  = (__nv_bfloat16*)sym_addr(g_Xn);
    __nv_bfloat16* Yn  = (__nv_bfloat16*)sym_addr(g_Yn);

    cudaFuncSetAttribute(proj_norm<0>, cudaFuncAttributeMaxDynamicSharedMemorySize, PROJ_SMEM);
    cudaFuncSetAttribute(proj_norm<1>, cudaFuncAttributeMaxDynamicSharedMemorySize, PROJ_SMEM);
    cudaFuncSetAttribute(gemm_big,     cudaFuncAttributeMaxDynamicSharedMemorySize, BIG_SMEM);

    // 0) conversions (single kernel)
    {
        const int total4 = (NROWS * DIM1 + NROWS * DIM2 + DOUT * DIM1 + DOUT * DIM2) / 4;
        conv_all<<<(total4 + 255) / 256, 256>>>(X, Y, Wx, Wy);
    }

    // 1,2) fused projection + normalize (also zeroes the sum accumulators)
    proj_norm<0><<<NROWS / 64, 512, PROJ_SMEM>>>(Xb, Wxb, DIM1, bx, Xn);
    proj_norm<1><<<NROWS / 64, 512, PROJ_SMEM>>>(Yb, Wyb, DIM2, by, Yn);

    // 3) big GEMM with fused exp/rowsum/colsum/diag  (sim = Xn @ Yn^T)
    gemm_big<<<dim3(NROWS / 128, NROWS / 128), 256, BIG_SMEM>>>(Xn, Yn);

    // 4) finalize
    finalize<<<NROWS / 256, 256>>>((float*)d_out);
}